// round 13
// baseline (speedup 1.0000x reference)
#include <cuda_runtime.h>
#include <cuda_bf16.h>
#include <cuda_fp16.h>
#include <math.h>

// ---------------------------------------------------------------------------
// GCN2 (GCNII) forward:  N=100000, E=1e6, IN=128, HID=64, OUT=64, L=4
//
// R10: SPMM fused into the tensor-core GEMM+BN kernel (per-block gather into
// smem, no global s/sh round-trip).
//   fork: [s2] CSR build (memset, count, scans, scatter)
//         [s1] mlp0 (HMMA; writes x, x0, fp16 shadow xh; zeroes BN slots)
//   per layer (s1): k_layer  (gather s -> smem; HMMA s@Wc; h + BN sums)
//                   k_post   (BN apply + residual + relu; refresh xh)
//   out = x @ W1 + b1 (HMMA from xh)
// ---------------------------------------------------------------------------

#define Nn   100000
#define Ee   1000000
#define HID  64
#define BN_EPS 1e-5f
#define Ll   4

#define RPB   512
#define NBLK  ((Nn + RPB - 1) / RPB)   // 196

// ---- scratch (device globals; allocation-free) ----
__device__ __align__(16) float   g_x  [Nn * HID];
__device__ __align__(16) float   g_x0 [Nn * HID];
__device__ __align__(16) float   g_h  [Nn * HID];
__device__ __align__(16) __half2 g_xh [Nn * 32];   // fp16 shadow of g_x
__device__ int2    g_edge[Ee];
__device__ int     g_cnt[Nn];
__device__ int     g_cur[Nn];
__device__ int     g_rowstart[Nn];
__device__ int     g_blocksum[NBLK];
__device__ int     g_blockoff[NBLK];
__device__ float   g_bnsum[Ll * HID];              // per-layer slots
__device__ float   g_bnsq [Ll * HID];

// ---------------------------------------------------------------------------
// CSR construction
// ---------------------------------------------------------------------------
__global__ void k_count(const int* __restrict__ ei) {
    int e = blockIdx.x * blockDim.x + threadIdx.x;
    if (e < Ee) atomicAdd(&g_cnt[ei[e]], 1);
}

__global__ void k_scanA() {
    __shared__ int sh[RPB];
    int r = blockIdx.x * RPB + threadIdx.x;
    sh[threadIdx.x] = (r < Nn) ? g_cnt[r] : 0;
    __syncthreads();
    for (int off = RPB / 2; off > 0; off >>= 1) {
        if (threadIdx.x < off) sh[threadIdx.x] += sh[threadIdx.x + off];
        __syncthreads();
    }
    if (threadIdx.x == 0) g_blocksum[blockIdx.x] = sh[0];
}

__global__ void k_scanB() {
    __shared__ int sh[256];
    int tid = threadIdx.x;
    int v = (tid < NBLK) ? g_blocksum[tid] : 0;
    sh[tid] = v;
    __syncthreads();
    for (int off = 1; off < 256; off <<= 1) {
        int t = (tid >= off) ? sh[tid - off] : 0;
        __syncthreads();
        sh[tid] += t;
        __syncthreads();
    }
    if (tid < NBLK) g_blockoff[tid] = sh[tid] - v;
}

__global__ void k_scanC() {
    __shared__ int sh[RPB];
    int tid = threadIdx.x;
    int r = blockIdx.x * RPB + tid;
    int v = (r < Nn) ? g_cnt[r] : 0;
    sh[tid] = v;
    __syncthreads();
    for (int off = 1; off < RPB; off <<= 1) {
        int t = (tid >= off) ? sh[tid - off] : 0;
        __syncthreads();
        sh[tid] += t;
        __syncthreads();
    }
    if (r < Nn) g_rowstart[r] = sh[tid] - v + g_blockoff[blockIdx.x];
}

__device__ __forceinline__ float dinv_of(int d) {
    return d > 0 ? rsqrtf((float)d) : 0.0f;
}

__global__ void k_scatter(const int* __restrict__ ei) {
    int e = blockIdx.x * blockDim.x + threadIdx.x;
    if (e >= Ee) return;
    int row = ei[e];
    int col = ei[Ee + e];
    int pos = g_rowstart[row] + atomicAdd(&g_cur[row], 1);
    float w = dinv_of(g_cnt[row]) * dinv_of(g_cnt[col]);
    g_edge[pos] = make_int2(col, __float_as_int(w));
}

// ---------------------------------------------------------------------------
// Tensor-core GEMM building blocks (mma.sync m16n8k16, fp16 in / fp32 acc)
// Block = 256 threads (8 warps), output tile 128 rows x 64 cols.
// Warp (wm = wid>>1, wn = wid&1) computes 32x32: 2 m16 x 4 n8 frags.
// ---------------------------------------------------------------------------
__device__ __forceinline__ void ldm_x4(unsigned r[4], const __half* p) {
    unsigned addr = (unsigned)__cvta_generic_to_shared(p);
    asm volatile("ldmatrix.sync.aligned.m8n8.x4.shared.b16 {%0,%1,%2,%3}, [%4];"
                 : "=r"(r[0]), "=r"(r[1]), "=r"(r[2]), "=r"(r[3]) : "r"(addr));
}
__device__ __forceinline__ void ldm_x4_t(unsigned r[4], const __half* p) {
    unsigned addr = (unsigned)__cvta_generic_to_shared(p);
    asm volatile("ldmatrix.sync.aligned.m8n8.x4.trans.shared.b16 {%0,%1,%2,%3}, [%4];"
                 : "=r"(r[0]), "=r"(r[1]), "=r"(r[2]), "=r"(r[3]) : "r"(addr));
}
__device__ __forceinline__ void mma16816(float4& d, const unsigned a[4],
                                         const unsigned b0, const unsigned b1) {
    asm volatile(
        "mma.sync.aligned.m16n8k16.row.col.f32.f16.f16.f32 "
        "{%0,%1,%2,%3}, {%4,%5,%6,%7}, {%8,%9}, {%0,%1,%2,%3};"
        : "+f"(d.x), "+f"(d.y), "+f"(d.z), "+f"(d.w)
        : "r"(a[0]), "r"(a[1]), "r"(a[2]), "r"(a[3]), "r"(b0), "r"(b1));
}

template <int KS, int SA>
__device__ __forceinline__ void warp_gemm(const __half* ash, const __half* wsh,
                                          int wm, int wn, int lane,
                                          float4 acc[2][4]) {
    #pragma unroll
    for (int kk = 0; kk < KS; kk++) {
        unsigned a[2][4];
        #pragma unroll
        for (int mi = 0; mi < 2; mi++)
            ldm_x4(a[mi], &ash[(wm * 32 + mi * 16 + (lane & 15)) * SA
                               + kk * 16 + (lane >> 4) * 8]);
        unsigned b[4][2];
        #pragma unroll
        for (int g = 0; g < 2; g++) {
            unsigned t[4];
            ldm_x4_t(t, &wsh[(kk * 16 + (lane & 15)) * 72
                             + wn * 32 + g * 16 + (lane >> 4) * 8]);
            b[2 * g][0] = t[0]; b[2 * g][1] = t[1];
            b[2 * g + 1][0] = t[2]; b[2 * g + 1][1] = t[3];
        }
        #pragma unroll
        for (int mi = 0; mi < 2; mi++)
            #pragma unroll
            for (int nj = 0; nj < 4; nj++)
                mma16816(acc[mi][nj], a[mi], b[nj][0], b[nj][1]);
    }
}

// --- layer 0: x = relu(X@W0 + b0); x0 = x; xh = fp16(x); zero BN slots -----
__global__ void k_mlp0(const float* __restrict__ X,
                       const float* __restrict__ W0,
                       const float* __restrict__ b0) {
    extern __shared__ __half smh[];
    __half* ash = smh;              // 128 x 136
    __half* wsh = smh + 128 * 136;  // 128 x 72
    const int tid = threadIdx.x, lane = tid & 31, wid = tid >> 5;
    const int row0 = blockIdx.x * 128;

    if (blockIdx.x == 0) {          // tid covers Ll*HID = 256 exactly
        g_bnsum[tid] = 0.0f;
        g_bnsq [tid] = 0.0f;
    }

    for (int i = tid; i < 4096; i += 256) {
        float2 w = ((const float2*)W0)[i];
        ((__half2*)wsh)[(i >> 5) * 36 + (i & 31)] = __floats2half2_rn(w.x, w.y);
    }
    for (int i = tid; i < 4096; i += 256) {
        int r = i >> 5, c4 = i & 31;
        int gr = row0 + r;
        float4 v = make_float4(0.f, 0.f, 0.f, 0.f);
        if (gr < Nn) v = ((const float4*)X)[gr * 32 + c4];
        __half2 h0 = __floats2half2_rn(v.x, v.y);
        __half2 h1 = __floats2half2_rn(v.z, v.w);
        uint2 p = make_uint2(*(unsigned*)&h0, *(unsigned*)&h1);
        *(uint2*)&ash[r * 136 + c4 * 4] = p;
    }
    __syncthreads();

    const int wm = wid >> 1, wn = wid & 1;
    float4 acc[2][4];
    #pragma unroll
    for (int mi = 0; mi < 2; mi++)
        #pragma unroll
        for (int nj = 0; nj < 4; nj++) acc[mi][nj] = make_float4(0.f, 0.f, 0.f, 0.f);

    warp_gemm<8, 136>(ash, wsh, wm, wn, lane, acc);

    #pragma unroll
    for (int mi = 0; mi < 2; mi++) {
        #pragma unroll
        for (int nj = 0; nj < 4; nj++) {
            int col = wn * 32 + nj * 8 + (lane & 3) * 2;
            float2 bv = *(const float2*)&b0[col];
            int r0 = row0 + wm * 32 + mi * 16 + (lane >> 2);
            int r1 = r0 + 8;
            if (r0 < Nn) {
                float2 v = make_float2(fmaxf(acc[mi][nj].x + bv.x, 0.f),
                                       fmaxf(acc[mi][nj].y + bv.y, 0.f));
                int idx = r0 * 32 + (col >> 1);
                ((float2*)g_x)[idx] = v;  ((float2*)g_x0)[idx] = v;
                g_xh[idx] = __floats2half2_rn(v.x, v.y);
            }
            if (r1 < Nn) {
                float2 v = make_float2(fmaxf(acc[mi][nj].z + bv.x, 0.f),
                                       fmaxf(acc[mi][nj].w + bv.y, 0.f));
                int idx = r1 * 32 + (col >> 1);
                ((float2*)g_x)[idx] = v;  ((float2*)g_x0)[idx] = v;
                g_xh[idx] = __floats2half2_rn(v.x, v.y);
            }
        }
    }
}

// --- fused layer: gather s (CSR, fp16 operand) -> smem; HMMA s@Wc;
//     h = (1-b)*s + b*(s@Wc) -> g_h; BN partial sums into slot -------------
__global__ void k_layer(const float* __restrict__ Wc, float beta, int slot) {
    extern __shared__ __half smh[];
    __half* ash = smh;                          // 128 x 72 fp16 s tile
    __half* wsh = smh + 128 * 72;               // 64 x 72 fp16 W
    float*  s32 = (float*)(smh + 128 * 72 + 64 * 72);  // 128 x 64 fp32 s
    __shared__ float bsum[HID], bsq[HID];
    const int tid = threadIdx.x, lane = tid & 31, wid = tid >> 5;
    const int row0 = blockIdx.x * 128;
    if (tid < HID) { bsum[tid] = 0.f; bsq[tid] = 0.f; }

    for (int i = tid; i < 2048; i += 256) {     // Wc fp32 -> fp16
        float2 w = ((const float2*)Wc)[i];
        ((__half2*)wsh)[(i >> 5) * 36 + (i & 31)] = __floats2half2_rn(w.x, w.y);
    }

    // ---- phase 1: SPMM gather for this block's 128 rows (warp = row) ----
    for (int rr = wid; rr < 128; rr += 8) {
        int gr = row0 + rr;
        float2 s = make_float2(0.f, 0.f);
        if (gr < Nn) {
            int start = g_rowstart[gr];
            int deg   = g_cnt[gr];
            float2 acc = make_float2(0.f, 0.f);
            #pragma unroll 4
            for (int j = 0; j < deg; j++) {
                int2 em = __ldg(&g_edge[start + j]);
                float w = __int_as_float(em.y);
                float2 v = __half22float2(__ldg(&g_xh[em.x * 32 + lane]));
                acc.x = fmaf(w, v.x, acc.x);
                acc.y = fmaf(w, v.y, acc.y);
            }
            float2 x0v = __ldg(&((const float2*)g_x0)[gr * 32 + lane]);
            s.x = 0.9f * acc.x + 0.1f * x0v.x;
            s.y = 0.9f * acc.y + 0.1f * x0v.y;
        }
        *(__half2*)&ash[rr * 72 + lane * 2] = __floats2half2_rn(s.x, s.y);
        *(float2*)&s32[rr * 64 + lane * 2] = s;
    }
    __syncthreads();

    // ---- phase 2: HMMA ----
    const int wm = wid >> 1, wn = wid & 1;
    float4 acc[2][4];
    #pragma unroll
    for (int mi = 0; mi < 2; mi++)
        #pragma unroll
        for (int nj = 0; nj < 4; nj++) acc[mi][nj] = make_float4(0.f, 0.f, 0.f, 0.f);

    warp_gemm<4, 72>(ash, wsh, wm, wn, lane, acc);

    // ---- epilogue: h, BN sums ----
    const float ombeta = 1.0f - beta;
    float lsum[8], lsq[8];
    #pragma unroll
    for (int k = 0; k < 8; k++) { lsum[k] = 0.f; lsq[k] = 0.f; }

    #pragma unroll
    for (int mi = 0; mi < 2; mi++) {
        #pragma unroll
        for (int nj = 0; nj < 4; nj++) {
            int col = wn * 32 + nj * 8 + (lane & 3) * 2;
            int lr0 = wm * 32 + mi * 16 + (lane >> 2);
            int lr1 = lr0 + 8;
            int r0 = row0 + lr0, r1 = row0 + lr1;
            if (r0 < Nn) {
                float2 s = *(const float2*)&s32[lr0 * 64 + col];
                float hx = ombeta * s.x + beta * acc[mi][nj].x;
                float hy = ombeta * s.y + beta * acc[mi][nj].y;
                ((float2*)g_h)[r0 * 32 + (col >> 1)] = make_float2(hx, hy);
                lsum[nj * 2] += hx;  lsum[nj * 2 + 1] += hy;
                lsq [nj * 2] += hx * hx;  lsq[nj * 2 + 1] += hy * hy;
            }
            if (r1 < Nn) {
                float2 s = *(const float2*)&s32[lr1 * 64 + col];
                float hx = ombeta * s.x + beta * acc[mi][nj].z;
                float hy = ombeta * s.y + beta * acc[mi][nj].w;
                ((float2*)g_h)[r1 * 32 + (col >> 1)] = make_float2(hx, hy);
                lsum[nj * 2] += hx;  lsum[nj * 2 + 1] += hy;
                lsq [nj * 2] += hx * hx;  lsq[nj * 2 + 1] += hy * hy;
            }
        }
    }
    #pragma unroll
    for (int off = 16; off >= 4; off >>= 1) {
        #pragma unroll
        for (int k = 0; k < 8; k++) {
            lsum[k] += __shfl_xor_sync(0xffffffffu, lsum[k], off);
            lsq [k] += __shfl_xor_sync(0xffffffffu, lsq [k], off);
        }
    }
    if ((lane >> 2) == 0) {
        #pragma unroll
        for (int nj = 0; nj < 4; nj++) {
            #pragma unroll
            for (int p = 0; p < 2; p++) {
                int col = wn * 32 + nj * 8 + (lane & 3) * 2 + p;
                atomicAdd(&bsum[col], lsum[nj * 2 + p]);
                atomicAdd(&bsq [col], lsq [nj * 2 + p]);
            }
        }
    }
    __syncthreads();
    if (tid < HID) {
        atomicAdd(&g_bnsum[slot * HID + tid], bsum[tid]);
        atomicAdd(&g_bnsq [slot * HID + tid], bsq [tid]);
    }
}

// --- BN apply + residual + relu -> g_x, g_xh -------------------------------
__global__ void k_post(const float* __restrict__ gamma,
                       const float* __restrict__ bb, int slot) {
    int t = blockIdx.x * 256 + threadIdx.x;
    int n = t >> 4, q = t & 15;
    if (n >= Nn) return;
    int c = q * 4;
    int idx = n * HID + c;
    const float invN = 1.0f / (float)Nn;
    const float* bns = &g_bnsum[slot * HID];
    const float* bnq = &g_bnsq [slot * HID];

    float4 h  = *(float4*)&g_h[idx];
    float4 xo = *(float4*)&g_x[idx];
    float4 v;
    {
        float m = bns[c + 0] * invN;
        float var = bnq[c + 0] * invN - m * m;
        v.x = (h.x - m) * rsqrtf(var + BN_EPS) * __ldg(&gamma[c + 0]) + __ldg(&bb[c + 0]) + xo.x;
    }
    {
        float m = bns[c + 1] * invN;
        float var = bnq[c + 1] * invN - m * m;
        v.y = (h.y - m) * rsqrtf(var + BN_EPS) * __ldg(&gamma[c + 1]) + __ldg(&bb[c + 1]) + xo.y;
    }
    {
        float m = bns[c + 2] * invN;
        float var = bnq[c + 2] * invN - m * m;
        v.z = (h.z - m) * rsqrtf(var + BN_EPS) * __ldg(&gamma[c + 2]) + __ldg(&bb[c + 2]) + xo.z;
    }
    {
        float m = bns[c + 3] * invN;
        float var = bnq[c + 3] * invN - m * m;
        v.w = (h.w - m) * rsqrtf(var + BN_EPS) * __ldg(&gamma[c + 3]) + __ldg(&bb[c + 3]) + xo.w;
    }
    v.x = fmaxf(v.x, 0.f); v.y = fmaxf(v.y, 0.f);
    v.z = fmaxf(v.z, 0.f); v.w = fmaxf(v.w, 0.f);
    *(float4*)&g_x[idx] = v;
    __half2 h0 = __floats2half2_rn(v.x, v.y);
    __half2 h1 = __floats2half2_rn(v.z, v.w);
    uint2 p = make_uint2(*(unsigned*)&h0, *(unsigned*)&h1);
    *(uint2*)&g_xh[n * 32 + q * 2] = p;
}

// --- final: out = x @ W1 + b1  (K = 64, from fp16 shadow) ------------------
__global__ void k_out(const float* __restrict__ W1,
                      const float* __restrict__ b1,
                      float* __restrict__ out) {
    extern __shared__ __half smh[];
    __half* ash = smh;             // 128 x 72
    __half* wsh = smh + 128 * 72;  // 64 x 72
    const int tid = threadIdx.x, lane = tid & 31, wid = tid >> 5;
    const int row0 = blockIdx.x * 128;

    for (int i = tid; i < 2048; i += 256) {
        float2 w = ((const float2*)W1)[i];
        ((__half2*)wsh)[(i >> 5) * 36 + (i & 31)] = __floats2half2_rn(w.x, w.y);
    }
    for (int i = tid; i < 1024; i += 256) {
        int r = i >> 3, c = i & 7;
        int gr = row0 + r;
        uint4 v = make_uint4(0, 0, 0, 0);
        if (gr < Nn) v = ((const uint4*)g_xh)[gr * 8 + c];
        *(uint4*)&ash[r * 72 + c * 8] = v;
    }
    __syncthreads();

    const int wm = wid >> 1, wn = wid & 1;
    float4 acc[2][4];
    #pragma unroll
    for (int mi = 0; mi < 2; mi++)
        #pragma unroll
        for (int nj = 0; nj < 4; nj++) acc[mi][nj] = make_float4(0.f, 0.f, 0.f, 0.f);

    warp_gemm<4, 72>(ash, wsh, wm, wn, lane, acc);

    #pragma unroll
    for (int mi = 0; mi < 2; mi++) {
        #pragma unroll
        for (int nj = 0; nj < 4; nj++) {
            int col = wn * 32 + nj * 8 + (lane & 3) * 2;
            float2 bv = *(const float2*)&b1[col];
            int r0 = row0 + wm * 32 + mi * 16 + (lane >> 2);
            int r1 = r0 + 8;
            if (r0 < Nn)
                ((float2*)out)[r0 * 32 + (col >> 1)] =
                    make_float2(acc[mi][nj].x + bv.x, acc[mi][nj].y + bv.y);
            if (r1 < Nn)
                ((float2*)out)[r1 * 32 + (col >> 1)] =
                    make_float2(acc[mi][nj].z + bv.x, acc[mi][nj].w + bv.y);
        }
    }
}

// ---------------------------------------------------------------------------
extern "C" void kernel_launch(void* const* d_in, const int* in_sizes, int n_in,
                              void* d_out, int out_size) {
    const float* x     = (const float*)d_in[0];
    const int*   ei    = (const int*)  d_in[1];
    const float* W0    = (const float*)d_in[2];
    const float* b0    = (const float*)d_in[3];
    const float* convw = (const float*)d_in[4];
    const float* gamma = (const float*)d_in[5];
    const float* betab = (const float*)d_in[6];
    const float* W1    = (const float*)d_in[7];
    const float* b1    = (const float*)d_in[8];
    float* out = (float*)d_out;

    static cudaStream_t s1 = nullptr, s2 = nullptr;
    static cudaEvent_t  evA = nullptr, evCSR = nullptr, evEnd = nullptr;
    static void *p_cnt = nullptr, *p_cur = nullptr;
    if (s1 == nullptr) {
        cudaStreamCreateWithFlags(&s1, cudaStreamNonBlocking);
        cudaStreamCreateWithFlags(&s2, cudaStreamNonBlocking);
        cudaEventCreateWithFlags(&evA,   cudaEventDisableTiming);
        cudaEventCreateWithFlags(&evCSR, cudaEventDisableTiming);
        cudaEventCreateWithFlags(&evEnd, cudaEventDisableTiming);
        cudaGetSymbolAddress(&p_cnt, g_cnt);
        cudaGetSymbolAddress(&p_cur, g_cur);
    }

    const int SMEM_MLP0  = (128 * 136 + 128 * 72) * 2;             // 53248 B
    const int SMEM_G64   = (128 * 72  + 64  * 72) * 2;             // 27648 B
    const int SMEM_LAYER = SMEM_G64 + 128 * 64 * 4;                // 60416 B
    cudaFuncSetAttribute(k_mlp0,  cudaFuncAttributeMaxDynamicSharedMemorySize, SMEM_MLP0);
    cudaFuncSetAttribute(k_layer, cudaFuncAttributeMaxDynamicSharedMemorySize, SMEM_LAYER);
    cudaFuncSetAttribute(k_out,   cudaFuncAttributeMaxDynamicSharedMemorySize, SMEM_G64);

    const int GB = (Nn + 127) / 128;          // 782
    const int EB = (Ee + 255) / 256;

    cudaEventRecord(evA, 0);
    cudaStreamWaitEvent(s1, evA, 0);
    cudaStreamWaitEvent(s2, evA, 0);

    cudaMemsetAsync(p_cnt, 0, Nn * sizeof(int), s2);
    cudaMemsetAsync(p_cur, 0, Nn * sizeof(int), s2);
    k_count  <<<EB, 256, 0, s2>>>(ei);
    k_scanA  <<<NBLK, RPB, 0, s2>>>();
    k_scanB  <<<1, 256, 0, s2>>>();
    k_scanC  <<<NBLK, RPB, 0, s2>>>();
    k_scatter<<<EB, 256, 0, s2>>>(ei);
    cudaEventRecord(evCSR, s2);

    k_mlp0<<<GB, 256, SMEM_MLP0, s1>>>(x, W0, b0);

    cudaStreamWaitEvent(s1, evCSR, 0);

    for (int i = 0; i < 4; i++) {
        float beta = (float)log(0.5 / (double)(i + 1) + 1.0);
        k_layer<<<GB, 256, SMEM_LAYER, s1>>>(convw + i * HID * HID, beta, i);
        k_post<<<(Nn * 16 + 255) / 256, 256, 0, s1>>>(gamma + i * HID, betab + i * HID, i);
    }

    k_out<<<GB, 256, SMEM_G64, s1>>>(W1, b1, out);

    cudaEventRecord(evEnd, s1);
    cudaStreamWaitEvent(0, evEnd, 0);
}

// round 14
// speedup vs baseline: 1.0043x; 1.0043x over previous
#include <cuda_runtime.h>
#include <cuda_bf16.h>
#include <cuda_fp16.h>
#include <math.h>

// ---------------------------------------------------------------------------
// GCN2 (GCNII) forward:  N=100000, E=1e6, IN=128, HID=64, OUT=64, L=4
//
// R10: SPMM fused into the tensor-core GEMM+BN kernel (per-block gather into
// smem, no global s/sh round-trip).
//   fork: [s2] CSR build (memset, count, scans, scatter)
//         [s1] mlp0 (HMMA; writes x, x0, fp16 shadow xh; zeroes BN slots)
//   per layer (s1): k_layer  (gather s -> smem; HMMA s@Wc; h + BN sums)
//                   k_post   (BN apply + residual + relu; refresh xh)
//   out = x @ W1 + b1 (HMMA from xh)
// ---------------------------------------------------------------------------

#define Nn   100000
#define Ee   1000000
#define HID  64
#define BN_EPS 1e-5f
#define Ll   4

#define RPB   512
#define NBLK  ((Nn + RPB - 1) / RPB)   // 196

// ---- scratch (device globals; allocation-free) ----
__device__ __align__(16) float   g_x  [Nn * HID];
__device__ __align__(16) float   g_x0 [Nn * HID];
__device__ __align__(16) float   g_h  [Nn * HID];
__device__ __align__(16) __half2 g_xh [Nn * 32];   // fp16 shadow of g_x
__device__ int2    g_edge[Ee];
__device__ int     g_cnt[Nn];
__device__ int     g_cur[Nn];
__device__ int     g_rowstart[Nn];
__device__ int     g_blocksum[NBLK];
__device__ int     g_blockoff[NBLK];
__device__ float   g_bnsum[Ll * HID];              // per-layer slots
__device__ float   g_bnsq [Ll * HID];

// ---------------------------------------------------------------------------
// CSR construction
// ---------------------------------------------------------------------------
__global__ void k_count(const int* __restrict__ ei) {
    int e = blockIdx.x * blockDim.x + threadIdx.x;
    if (e < Ee) atomicAdd(&g_cnt[ei[e]], 1);
}

__global__ void k_scanA() {
    __shared__ int sh[RPB];
    int r = blockIdx.x * RPB + threadIdx.x;
    sh[threadIdx.x] = (r < Nn) ? g_cnt[r] : 0;
    __syncthreads();
    for (int off = RPB / 2; off > 0; off >>= 1) {
        if (threadIdx.x < off) sh[threadIdx.x] += sh[threadIdx.x + off];
        __syncthreads();
    }
    if (threadIdx.x == 0) g_blocksum[blockIdx.x] = sh[0];
}

__global__ void k_scanB() {
    __shared__ int sh[256];
    int tid = threadIdx.x;
    int v = (tid < NBLK) ? g_blocksum[tid] : 0;
    sh[tid] = v;
    __syncthreads();
    for (int off = 1; off < 256; off <<= 1) {
        int t = (tid >= off) ? sh[tid - off] : 0;
        __syncthreads();
        sh[tid] += t;
        __syncthreads();
    }
    if (tid < NBLK) g_blockoff[tid] = sh[tid] - v;
}

__global__ void k_scanC() {
    __shared__ int sh[RPB];
    int tid = threadIdx.x;
    int r = blockIdx.x * RPB + tid;
    int v = (r < Nn) ? g_cnt[r] : 0;
    sh[tid] = v;
    __syncthreads();
    for (int off = 1; off < RPB; off <<= 1) {
        int t = (tid >= off) ? sh[tid - off] : 0;
        __syncthreads();
        sh[tid] += t;
        __syncthreads();
    }
    if (r < Nn) g_rowstart[r] = sh[tid] - v + g_blockoff[blockIdx.x];
}

__device__ __forceinline__ float dinv_of(int d) {
    return d > 0 ? rsqrtf((float)d) : 0.0f;
}

__global__ void k_scatter(const int* __restrict__ ei) {
    int e = blockIdx.x * blockDim.x + threadIdx.x;
    if (e >= Ee) return;
    int row = ei[e];
    int col = ei[Ee + e];
    int pos = g_rowstart[row] + atomicAdd(&g_cur[row], 1);
    float w = dinv_of(g_cnt[row]) * dinv_of(g_cnt[col]);
    g_edge[pos] = make_int2(col, __float_as_int(w));
}

// ---------------------------------------------------------------------------
// Tensor-core GEMM building blocks (mma.sync m16n8k16, fp16 in / fp32 acc)
// Block = 256 threads (8 warps), output tile 128 rows x 64 cols.
// Warp (wm = wid>>1, wn = wid&1) computes 32x32: 2 m16 x 4 n8 frags.
// ---------------------------------------------------------------------------
__device__ __forceinline__ void ldm_x4(unsigned r[4], const __half* p) {
    unsigned addr = (unsigned)__cvta_generic_to_shared(p);
    asm volatile("ldmatrix.sync.aligned.m8n8.x4.shared.b16 {%0,%1,%2,%3}, [%4];"
                 : "=r"(r[0]), "=r"(r[1]), "=r"(r[2]), "=r"(r[3]) : "r"(addr));
}
__device__ __forceinline__ void ldm_x4_t(unsigned r[4], const __half* p) {
    unsigned addr = (unsigned)__cvta_generic_to_shared(p);
    asm volatile("ldmatrix.sync.aligned.m8n8.x4.trans.shared.b16 {%0,%1,%2,%3}, [%4];"
                 : "=r"(r[0]), "=r"(r[1]), "=r"(r[2]), "=r"(r[3]) : "r"(addr));
}
__device__ __forceinline__ void mma16816(float4& d, const unsigned a[4],
                                         const unsigned b0, const unsigned b1) {
    asm volatile(
        "mma.sync.aligned.m16n8k16.row.col.f32.f16.f16.f32 "
        "{%0,%1,%2,%3}, {%4,%5,%6,%7}, {%8,%9}, {%0,%1,%2,%3};"
        : "+f"(d.x), "+f"(d.y), "+f"(d.z), "+f"(d.w)
        : "r"(a[0]), "r"(a[1]), "r"(a[2]), "r"(a[3]), "r"(b0), "r"(b1));
}

template <int KS, int SA>
__device__ __forceinline__ void warp_gemm(const __half* ash, const __half* wsh,
                                          int wm, int wn, int lane,
                                          float4 acc[2][4]) {
    #pragma unroll
    for (int kk = 0; kk < KS; kk++) {
        unsigned a[2][4];
        #pragma unroll
        for (int mi = 0; mi < 2; mi++)
            ldm_x4(a[mi], &ash[(wm * 32 + mi * 16 + (lane & 15)) * SA
                               + kk * 16 + (lane >> 4) * 8]);
        unsigned b[4][2];
        #pragma unroll
        for (int g = 0; g < 2; g++) {
            unsigned t[4];
            ldm_x4_t(t, &wsh[(kk * 16 + (lane & 15)) * 72
                             + wn * 32 + g * 16 + (lane >> 4) * 8]);
            b[2 * g][0] = t[0]; b[2 * g][1] = t[1];
            b[2 * g + 1][0] = t[2]; b[2 * g + 1][1] = t[3];
        }
        #pragma unroll
        for (int mi = 0; mi < 2; mi++)
            #pragma unroll
            for (int nj = 0; nj < 4; nj++)
                mma16816(acc[mi][nj], a[mi], b[nj][0], b[nj][1]);
    }
}

// --- layer 0: x = relu(X@W0 + b0); x0 = x; xh = fp16(x); zero BN slots -----
__global__ void k_mlp0(const float* __restrict__ X,
                       const float* __restrict__ W0,
                       const float* __restrict__ b0) {
    extern __shared__ __half smh[];
    __half* ash = smh;              // 128 x 136
    __half* wsh = smh + 128 * 136;  // 128 x 72
    const int tid = threadIdx.x, lane = tid & 31, wid = tid >> 5;
    const int row0 = blockIdx.x * 128;

    if (blockIdx.x == 0) {          // tid covers Ll*HID = 256 exactly
        g_bnsum[tid] = 0.0f;
        g_bnsq [tid] = 0.0f;
    }

    for (int i = tid; i < 4096; i += 256) {
        float2 w = ((const float2*)W0)[i];
        ((__half2*)wsh)[(i >> 5) * 36 + (i & 31)] = __floats2half2_rn(w.x, w.y);
    }
    for (int i = tid; i < 4096; i += 256) {
        int r = i >> 5, c4 = i & 31;
        int gr = row0 + r;
        float4 v = make_float4(0.f, 0.f, 0.f, 0.f);
        if (gr < Nn) v = ((const float4*)X)[gr * 32 + c4];
        __half2 h0 = __floats2half2_rn(v.x, v.y);
        __half2 h1 = __floats2half2_rn(v.z, v.w);
        uint2 p = make_uint2(*(unsigned*)&h0, *(unsigned*)&h1);
        *(uint2*)&ash[r * 136 + c4 * 4] = p;
    }
    __syncthreads();

    const int wm = wid >> 1, wn = wid & 1;
    float4 acc[2][4];
    #pragma unroll
    for (int mi = 0; mi < 2; mi++)
        #pragma unroll
        for (int nj = 0; nj < 4; nj++) acc[mi][nj] = make_float4(0.f, 0.f, 0.f, 0.f);

    warp_gemm<8, 136>(ash, wsh, wm, wn, lane, acc);

    #pragma unroll
    for (int mi = 0; mi < 2; mi++) {
        #pragma unroll
        for (int nj = 0; nj < 4; nj++) {
            int col = wn * 32 + nj * 8 + (lane & 3) * 2;
            float2 bv = *(const float2*)&b0[col];
            int r0 = row0 + wm * 32 + mi * 16 + (lane >> 2);
            int r1 = r0 + 8;
            if (r0 < Nn) {
                float2 v = make_float2(fmaxf(acc[mi][nj].x + bv.x, 0.f),
                                       fmaxf(acc[mi][nj].y + bv.y, 0.f));
                int idx = r0 * 32 + (col >> 1);
                ((float2*)g_x)[idx] = v;  ((float2*)g_x0)[idx] = v;
                g_xh[idx] = __floats2half2_rn(v.x, v.y);
            }
            if (r1 < Nn) {
                float2 v = make_float2(fmaxf(acc[mi][nj].z + bv.x, 0.f),
                                       fmaxf(acc[mi][nj].w + bv.y, 0.f));
                int idx = r1 * 32 + (col >> 1);
                ((float2*)g_x)[idx] = v;  ((float2*)g_x0)[idx] = v;
                g_xh[idx] = __floats2half2_rn(v.x, v.y);
            }
        }
    }
}

// --- fused layer: gather s (CSR, fp16 operand) -> smem; HMMA s@Wc;
//     h = (1-b)*s + b*(s@Wc) -> g_h; BN partial sums into slot -------------
__global__ void k_layer(const float* __restrict__ Wc, float beta, int slot) {
    extern __shared__ __half smh[];
    __half* ash = smh;                          // 128 x 72 fp16 s tile
    __half* wsh = smh + 128 * 72;               // 64 x 72 fp16 W
    float*  s32 = (float*)(smh + 128 * 72 + 64 * 72);  // 128 x 64 fp32 s
    __shared__ float bsum[HID], bsq[HID];
    const int tid = threadIdx.x, lane = tid & 31, wid = tid >> 5;
    const int row0 = blockIdx.x * 128;
    if (tid < HID) { bsum[tid] = 0.f; bsq[tid] = 0.f; }

    for (int i = tid; i < 2048; i += 256) {     // Wc fp32 -> fp16
        float2 w = ((const float2*)Wc)[i];
        ((__half2*)wsh)[(i >> 5) * 36 + (i & 31)] = __floats2half2_rn(w.x, w.y);
    }

    // ---- phase 1: SPMM gather for this block's 128 rows (warp = row) ----
    for (int rr = wid; rr < 128; rr += 8) {
        int gr = row0 + rr;
        float2 s = make_float2(0.f, 0.f);
        if (gr < Nn) {
            int start = g_rowstart[gr];
            int deg   = g_cnt[gr];
            float2 acc = make_float2(0.f, 0.f);
            #pragma unroll 4
            for (int j = 0; j < deg; j++) {
                int2 em = __ldg(&g_edge[start + j]);
                float w = __int_as_float(em.y);
                float2 v = __half22float2(__ldg(&g_xh[em.x * 32 + lane]));
                acc.x = fmaf(w, v.x, acc.x);
                acc.y = fmaf(w, v.y, acc.y);
            }
            float2 x0v = __ldg(&((const float2*)g_x0)[gr * 32 + lane]);
            s.x = 0.9f * acc.x + 0.1f * x0v.x;
            s.y = 0.9f * acc.y + 0.1f * x0v.y;
        }
        *(__half2*)&ash[rr * 72 + lane * 2] = __floats2half2_rn(s.x, s.y);
        *(float2*)&s32[rr * 64 + lane * 2] = s;
    }
    __syncthreads();

    // ---- phase 2: HMMA ----
    const int wm = wid >> 1, wn = wid & 1;
    float4 acc[2][4];
    #pragma unroll
    for (int mi = 0; mi < 2; mi++)
        #pragma unroll
        for (int nj = 0; nj < 4; nj++) acc[mi][nj] = make_float4(0.f, 0.f, 0.f, 0.f);

    warp_gemm<4, 72>(ash, wsh, wm, wn, lane, acc);

    // ---- epilogue: h, BN sums ----
    const float ombeta = 1.0f - beta;
    float lsum[8], lsq[8];
    #pragma unroll
    for (int k = 0; k < 8; k++) { lsum[k] = 0.f; lsq[k] = 0.f; }

    #pragma unroll
    for (int mi = 0; mi < 2; mi++) {
        #pragma unroll
        for (int nj = 0; nj < 4; nj++) {
            int col = wn * 32 + nj * 8 + (lane & 3) * 2;
            int lr0 = wm * 32 + mi * 16 + (lane >> 2);
            int lr1 = lr0 + 8;
            int r0 = row0 + lr0, r1 = row0 + lr1;
            if (r0 < Nn) {
                float2 s = *(const float2*)&s32[lr0 * 64 + col];
                float hx = ombeta * s.x + beta * acc[mi][nj].x;
                float hy = ombeta * s.y + beta * acc[mi][nj].y;
                ((float2*)g_h)[r0 * 32 + (col >> 1)] = make_float2(hx, hy);
                lsum[nj * 2] += hx;  lsum[nj * 2 + 1] += hy;
                lsq [nj * 2] += hx * hx;  lsq[nj * 2 + 1] += hy * hy;
            }
            if (r1 < Nn) {
                float2 s = *(const float2*)&s32[lr1 * 64 + col];
                float hx = ombeta * s.x + beta * acc[mi][nj].z;
                float hy = ombeta * s.y + beta * acc[mi][nj].w;
                ((float2*)g_h)[r1 * 32 + (col >> 1)] = make_float2(hx, hy);
                lsum[nj * 2] += hx;  lsum[nj * 2 + 1] += hy;
                lsq [nj * 2] += hx * hx;  lsq[nj * 2 + 1] += hy * hy;
            }
        }
    }
    #pragma unroll
    for (int off = 16; off >= 4; off >>= 1) {
        #pragma unroll
        for (int k = 0; k < 8; k++) {
            lsum[k] += __shfl_xor_sync(0xffffffffu, lsum[k], off);
            lsq [k] += __shfl_xor_sync(0xffffffffu, lsq [k], off);
        }
    }
    if ((lane >> 2) == 0) {
        #pragma unroll
        for (int nj = 0; nj < 4; nj++) {
            #pragma unroll
            for (int p = 0; p < 2; p++) {
                int col = wn * 32 + nj * 8 + (lane & 3) * 2 + p;
                atomicAdd(&bsum[col], lsum[nj * 2 + p]);
                atomicAdd(&bsq [col], lsq [nj * 2 + p]);
            }
        }
    }
    __syncthreads();
    if (tid < HID) {
        atomicAdd(&g_bnsum[slot * HID + tid], bsum[tid]);
        atomicAdd(&g_bnsq [slot * HID + tid], bsq [tid]);
    }
}

// --- BN apply + residual + relu -> g_x, g_xh -------------------------------
__global__ void k_post(const float* __restrict__ gamma,
                       const float* __restrict__ bb, int slot) {
    int t = blockIdx.x * 256 + threadIdx.x;
    int n = t >> 4, q = t & 15;
    if (n >= Nn) return;
    int c = q * 4;
    int idx = n * HID + c;
    const float invN = 1.0f / (float)Nn;
    const float* bns = &g_bnsum[slot * HID];
    const float* bnq = &g_bnsq [slot * HID];

    float4 h  = *(float4*)&g_h[idx];
    float4 xo = *(float4*)&g_x[idx];
    float4 v;
    {
        float m = bns[c + 0] * invN;
        float var = bnq[c + 0] * invN - m * m;
        v.x = (h.x - m) * rsqrtf(var + BN_EPS) * __ldg(&gamma[c + 0]) + __ldg(&bb[c + 0]) + xo.x;
    }
    {
        float m = bns[c + 1] * invN;
        float var = bnq[c + 1] * invN - m * m;
        v.y = (h.y - m) * rsqrtf(var + BN_EPS) * __ldg(&gamma[c + 1]) + __ldg(&bb[c + 1]) + xo.y;
    }
    {
        float m = bns[c + 2] * invN;
        float var = bnq[c + 2] * invN - m * m;
        v.z = (h.z - m) * rsqrtf(var + BN_EPS) * __ldg(&gamma[c + 2]) + __ldg(&bb[c + 2]) + xo.z;
    }
    {
        float m = bns[c + 3] * invN;
        float var = bnq[c + 3] * invN - m * m;
        v.w = (h.w - m) * rsqrtf(var + BN_EPS) * __ldg(&gamma[c + 3]) + __ldg(&bb[c + 3]) + xo.w;
    }
    v.x = fmaxf(v.x, 0.f); v.y = fmaxf(v.y, 0.f);
    v.z = fmaxf(v.z, 0.f); v.w = fmaxf(v.w, 0.f);
    *(float4*)&g_x[idx] = v;
    __half2 h0 = __floats2half2_rn(v.x, v.y);
    __half2 h1 = __floats2half2_rn(v.z, v.w);
    uint2 p = make_uint2(*(unsigned*)&h0, *(unsigned*)&h1);
    *(uint2*)&g_xh[n * 32 + q * 2] = p;
}

// --- final: out = x @ W1 + b1  (K = 64, from fp16 shadow) ------------------
__global__ void k_out(const float* __restrict__ W1,
                      const float* __restrict__ b1,
                      float* __restrict__ out) {
    extern __shared__ __half smh[];
    __half* ash = smh;             // 128 x 72
    __half* wsh = smh + 128 * 72;  // 64 x 72
    const int tid = threadIdx.x, lane = tid & 31, wid = tid >> 5;
    const int row0 = blockIdx.x * 128;

    for (int i = tid; i < 2048; i += 256) {
        float2 w = ((const float2*)W1)[i];
        ((__half2*)wsh)[(i >> 5) * 36 + (i & 31)] = __floats2half2_rn(w.x, w.y);
    }
    for (int i = tid; i < 1024; i += 256) {
        int r = i >> 3, c = i & 7;
        int gr = row0 + r;
        uint4 v = make_uint4(0, 0, 0, 0);
        if (gr < Nn) v = ((const uint4*)g_xh)[gr * 8 + c];
        *(uint4*)&ash[r * 72 + c * 8] = v;
    }
    __syncthreads();

    const int wm = wid >> 1, wn = wid & 1;
    float4 acc[2][4];
    #pragma unroll
    for (int mi = 0; mi < 2; mi++)
        #pragma unroll
        for (int nj = 0; nj < 4; nj++) acc[mi][nj] = make_float4(0.f, 0.f, 0.f, 0.f);

    warp_gemm<4, 72>(ash, wsh, wm, wn, lane, acc);

    #pragma unroll
    for (int mi = 0; mi < 2; mi++) {
        #pragma unroll
        for (int nj = 0; nj < 4; nj++) {
            int col = wn * 32 + nj * 8 + (lane & 3) * 2;
            float2 bv = *(const float2*)&b1[col];
            int r0 = row0 + wm * 32 + mi * 16 + (lane >> 2);
            int r1 = r0 + 8;
            if (r0 < Nn)
                ((float2*)out)[r0 * 32 + (col >> 1)] =
                    make_float2(acc[mi][nj].x + bv.x, acc[mi][nj].y + bv.y);
            if (r1 < Nn)
                ((float2*)out)[r1 * 32 + (col >> 1)] =
                    make_float2(acc[mi][nj].z + bv.x, acc[mi][nj].w + bv.y);
        }
    }
}

// ---------------------------------------------------------------------------
extern "C" void kernel_launch(void* const* d_in, const int* in_sizes, int n_in,
                              void* d_out, int out_size) {
    const float* x     = (const float*)d_in[0];
    const int*   ei    = (const int*)  d_in[1];
    const float* W0    = (const float*)d_in[2];
    const float* b0    = (const float*)d_in[3];
    const float* convw = (const float*)d_in[4];
    const float* gamma = (const float*)d_in[5];
    const float* betab = (const float*)d_in[6];
    const float* W1    = (const float*)d_in[7];
    const float* b1    = (const float*)d_in[8];
    float* out = (float*)d_out;

    static cudaStream_t s1 = nullptr, s2 = nullptr;
    static cudaEvent_t  evA = nullptr, evCSR = nullptr, evEnd = nullptr;
    static void *p_cnt = nullptr, *p_cur = nullptr;
    if (s1 == nullptr) {
        cudaStreamCreateWithFlags(&s1, cudaStreamNonBlocking);
        cudaStreamCreateWithFlags(&s2, cudaStreamNonBlocking);
        cudaEventCreateWithFlags(&evA,   cudaEventDisableTiming);
        cudaEventCreateWithFlags(&evCSR, cudaEventDisableTiming);
        cudaEventCreateWithFlags(&evEnd, cudaEventDisableTiming);
        cudaGetSymbolAddress(&p_cnt, g_cnt);
        cudaGetSymbolAddress(&p_cur, g_cur);
    }

    const int SMEM_MLP0  = (128 * 136 + 128 * 72) * 2;             // 53248 B
    const int SMEM_G64   = (128 * 72  + 64  * 72) * 2;             // 27648 B
    const int SMEM_LAYER = SMEM_G64 + 128 * 64 * 4;                // 60416 B
    cudaFuncSetAttribute(k_mlp0,  cudaFuncAttributeMaxDynamicSharedMemorySize, SMEM_MLP0);
    cudaFuncSetAttribute(k_layer, cudaFuncAttributeMaxDynamicSharedMemorySize, SMEM_LAYER);
    cudaFuncSetAttribute(k_out,   cudaFuncAttributeMaxDynamicSharedMemorySize, SMEM_G64);

    const int GB = (Nn + 127) / 128;          // 782
    const int EB = (Ee + 255) / 256;

    cudaEventRecord(evA, 0);
    cudaStreamWaitEvent(s1, evA, 0);
    cudaStreamWaitEvent(s2, evA, 0);

    cudaMemsetAsync(p_cnt, 0, Nn * sizeof(int), s2);
    cudaMemsetAsync(p_cur, 0, Nn * sizeof(int), s2);
    k_count  <<<EB, 256, 0, s2>>>(ei);
    k_scanA  <<<NBLK, RPB, 0, s2>>>();
    k_scanB  <<<1, 256, 0, s2>>>();
    k_scanC  <<<NBLK, RPB, 0, s2>>>();
    k_scatter<<<EB, 256, 0, s2>>>(ei);
    cudaEventRecord(evCSR, s2);

    k_mlp0<<<GB, 256, SMEM_MLP0, s1>>>(x, W0, b0);

    cudaStreamWaitEvent(s1, evCSR, 0);

    for (int i = 0; i < 4; i++) {
        float beta = (float)log(0.5 / (double)(i + 1) + 1.0);
        k_layer<<<GB, 256, SMEM_LAYER, s1>>>(convw + i * HID * HID, beta, i);
        k_post<<<(Nn * 16 + 255) / 256, 256, 0, s1>>>(gamma + i * HID, betab + i * HID, i);
    }

    k_out<<<GB, 256, SMEM_G64, s1>>>(W1, b1, out);

    cudaEventRecord(evEnd, s1);
    cudaStreamWaitEvent(0, evEnd, 0);
}